// round 12
// baseline (speedup 1.0000x reference)
#include <cuda_runtime.h>
#include <math_constants.h>

#define N0 16384
#define N1 8192
#define N2 4096
#define N3 2048
#define R2C 4.0f
#define FPS_T 1024

// ---------------- device scratch (no allocations allowed) ----------------
__device__ float4 g_p4_0[N0];
__device__ float4 g_p4_1[N1];
__device__ float4 g_p4_2[N2];
__device__ float4 g_p4_3[N3];
__device__ int    g_sel0[N1];
__device__ int    g_sel1[N2];
__device__ int    g_sel2[N3];
__device__ int    g_sori[N0];     // per-level sorted->original index scratch
__device__ float4 g_h0[N0 * 4];   // 16 floats per point
__device__ float4 g_x1[N1 * 4];
__device__ float4 g_x2[N2 * 4];
__device__ float4 g_x3[N3 * 4];
__device__ float4 g_f2[N2 * 4];
__device__ float4 g_f1[N1 * 4];
__device__ float4 g_f0[N0 * 4];

// ---------------- packed f32x2 helpers (component-wise IEEE rn, identical to scalar) ----
__device__ __forceinline__ unsigned long long pk2(float lo, float hi) {
    unsigned long long r;
    asm("mov.b64 %0, {%1, %2};" : "=l"(r) : "f"(lo), "f"(hi));
    return r;
}
__device__ __forceinline__ void unpk2(unsigned long long v, float& lo, float& hi) {
    asm("mov.b64 {%0, %1}, %2;" : "=f"(lo), "=f"(hi) : "l"(v));
}
__device__ __forceinline__ unsigned long long add2(unsigned long long a, unsigned long long b) {
    unsigned long long r;
    asm("add.rn.f32x2 %0, %1, %2;" : "=l"(r) : "l"(a), "l"(b));
    return r;
}
__device__ __forceinline__ unsigned long long mul2(unsigned long long a, unsigned long long b) {
    unsigned long long r;
    asm("mul.rn.f32x2 %0, %1, %2;" : "=l"(r) : "l"(a), "l"(b));
    return r;
}

// ---------------- prep: pack pos + squared norm into float4 ----------------
__global__ void prep_kernel(const float* __restrict__ pos) {
    int i = blockIdx.x * blockDim.x + threadIdx.x;
    if (i >= N0) return;
    float x = pos[3 * i], y = pos[3 * i + 1], z = pos[3 * i + 2];
    float nb = __fadd_rn(__fadd_rn(__fmul_rn(x, x), __fmul_rn(y, y)), __fmul_rn(z, z));
    g_p4_0[i] = make_float4(x, y, z, nb);
}

// no-op kernel: shifts launch indices so the ncu capture slot lands on fps0
__global__ void warm_kernel() {}

__device__ __forceinline__ void load16(const float4* __restrict__ row, float* v) {
    float4 a = row[0], b = row[1], c = row[2], d = row[3];
    v[0] = a.x; v[1] = a.y; v[2] = a.z; v[3] = a.w;
    v[4] = b.x; v[5] = b.y; v[6] = b.z; v[7] = b.w;
    v[8] = c.x; v[9] = c.y; v[10] = c.z; v[11] = c.w;
    v[12] = d.x; v[13] = d.y; v[14] = d.z; v[15] = d.w;
}

__device__ __forceinline__ void store16(float4* __restrict__ row, const float* v) {
    row[0] = make_float4(v[0], v[1], v[2], v[3]);
    row[1] = make_float4(v[4], v[5], v[6], v[7]);
    row[2] = make_float4(v[8], v[9], v[10], v[11]);
    row[3] = make_float4(v[12], v[13], v[14], v[15]);
}

// ---------------- lin_in ----------------
__global__ void lin_in_kernel(const float* __restrict__ x,
                              const float* __restrict__ W0, const float* __restrict__ b0,
                              const float* __restrict__ W1, const float* __restrict__ b1) {
    __shared__ float sW0[256], sW1[256], sb0[16], sb1[16];
    int t = threadIdx.x;
    for (int i = t; i < 256; i += blockDim.x) { sW0[i] = W0[i]; sW1[i] = W1[i]; }
    if (t < 16) { sb0[t] = b0[t]; sb1[t] = b1[t]; }
    __syncthreads();
    int g = blockIdx.x * blockDim.x + t;
    if (g >= N0) return;
    float in[16], hid[16], out[16];
    load16((const float4*)(x + g * 16), in);
#pragma unroll
    for (int o = 0; o < 16; o++) hid[o] = sb0[o];
#pragma unroll
    for (int i = 0; i < 16; i++) {
        float v = in[i];
#pragma unroll
        for (int o = 0; o < 16; o++) hid[o] = fmaf(v, sW0[i * 16 + o], hid[o]);
    }
#pragma unroll
    for (int o = 0; o < 16; o++) hid[o] = fmaxf(hid[o], 0.0f);
#pragma unroll
    for (int o = 0; o < 16; o++) out[o] = sb1[o];
#pragma unroll
    for (int i = 0; i < 16; i++) {
        float v = hid[i];
#pragma unroll
        for (int o = 0; o < 16; o++) out[o] = fmaf(v, sW1[i * 16 + o], out[o]);
    }
#pragma unroll
    for (int o = 0; o < 16; o++) out[o] = fmaxf(out[o], 0.0f);
    store16(&g_h0[g * 4], out);
}

// ---------------- FPS: spatial sort + warp-AABB pruning + atomic-key argmax ----------
template <int GB>
__device__ __forceinline__ int mcell(float x, float y, float z) {
    const float inv = (float)(1 << GB) * (1.0f / 32.0f);
    int cx = min((1 << GB) - 1, max(0, (int)(x * inv)));
    int cy = min((1 << GB) - 1, max(0, (int)(y * inv)));
    int cz = min((1 << GB) - 1, max(0, (int)(z * inv)));
    int m = 0;
#pragma unroll
    for (int b = 0; b < GB; b++)
        m |= (((cx >> b) & 1) << (3 * b)) | (((cy >> b) & 1) << (3 * b + 1)) |
             (((cz >> b) & 1) << (3 * b + 2));
    return m;
}

// pair-interleaved float index for sorted point (thread tt, chunk slot kk)
template <int LOGP>
__device__ __forceinline__ int pair_fidx(int tt, int kk) {
    return (kk >> 1) * (2 * FPS_T) + 2 * tt + (kk & 1);
}

// NPTS points, select M, PTS = NPTS/1024 points per thread, GB grid bits per dim
template <int NPTS, int M, int PTS, int GB>
__global__ __launch_bounds__(FPS_T, 1)
void fps_kernel(const float4* __restrict__ p4, int* __restrict__ sel, int* __restrict__ sori) {
    constexpr int NCELL = 1 << (3 * GB);
    constexpr int LOGP = (PTS == 16) ? 4 : (PTS == 8) ? 3 : 2;
    __shared__ int s_hist[4096];
    __shared__ unsigned long long s_key[3];   // 3-slot rotating argmax accumulator
    __shared__ int s_misc[40];

    extern __shared__ float sm[];
    float* px = sm;
    float* py = sm + NPTS;
    float* pz = sm + 2 * NPTS;

    const int t = threadIdx.x;
    const int lane = t & 31;
    const int wid = t >> 5;

    // ---- phase 1: histogram ----
    for (int i = t; i < NCELL; i += FPS_T) s_hist[i] = 0;
    if (t < 3) s_key[t] = 0ull;
    __syncthreads();
    for (int i = t; i < NPTS; i += FPS_T) {
        float4 p = p4[i];
        atomicAdd(&s_hist[mcell<GB>(p.x, p.y, p.z)], 1);
    }
    __syncthreads();

    // ---- phase 2: exclusive block scan of s_hist[0..NCELL) ----
    {
        constexpr int PER = (NCELL + FPS_T - 1) / FPS_T;
        int base = t * PER;
        int vals[PER];
        int run = 0;
#pragma unroll
        for (int q = 0; q < PER; q++) {
            int v = (base + q < NCELL) ? s_hist[base + q] : 0;
            vals[q] = v;
            run += v;
        }
        int inc = run;
#pragma unroll
        for (int off = 1; off < 32; off <<= 1) {
            int nb = __shfl_up_sync(0xffffffffu, inc, off);
            if (lane >= off) inc += nb;
        }
        if (lane == 31) s_misc[8 + wid] = inc;
        __syncthreads();
        if (t < 32) {
            int w = s_misc[8 + t];
            int winc = w;
#pragma unroll
            for (int off = 1; off < 32; off <<= 1) {
                int nb = __shfl_up_sync(0xffffffffu, winc, off);
                if (t >= off) winc += nb;
            }
            s_misc[8 + t] = winc - w;
        }
        __syncthreads();
        int off0 = s_misc[8 + wid] + (inc - run);
#pragma unroll
        for (int q = 0; q < PER; q++) {
            if (base + q < NCELL) s_hist[base + q] = off0;
            off0 += vals[q];
        }
    }
    __syncthreads();

    // ---- phase 3: scatter into pair-interleaved smem layout ----
    for (int i = t; i < NPTS; i += FPS_T) {
        float4 p = p4[i];
        int d = atomicAdd(&s_hist[mcell<GB>(p.x, p.y, p.z)], 1);
        int tt = d >> LOGP;
        int kk = d & (PTS - 1);
        int fidx = pair_fidx<LOGP>(tt, kk);
        px[fidx] = p.x; py[fidx] = p.y; pz[fidx] = p.z;
        sori[d] = i;
        if (i == 0) s_misc[0] = d;
    }
    __syncthreads();

    // ---- phase 4: per-thread mind init + WARP-level AABB ----
    float mind[PTS];
    float lox = CUDART_INF_F, loy = CUDART_INF_F, loz = CUDART_INF_F;
    float hix = -CUDART_INF_F, hiy = -CUDART_INF_F, hiz = -CUDART_INF_F;
#pragma unroll
    for (int k = 0; k < PTS; k++) {
        int fidx = pair_fidx<LOGP>(t, k);
        float X = px[fidx], Y = py[fidx], Z = pz[fidx];
        lox = fminf(lox, X); hix = fmaxf(hix, X);
        loy = fminf(loy, Y); hiy = fmaxf(hiy, Y);
        loz = fminf(loz, Z); hiz = fmaxf(hiz, Z);
        mind[k] = CUDART_INF_F;
    }
#pragma unroll
    for (int off = 16; off; off >>= 1) {
        lox = fminf(lox, __shfl_xor_sync(0xffffffffu, lox, off));
        hix = fmaxf(hix, __shfl_xor_sync(0xffffffffu, hix, off));
        loy = fminf(loy, __shfl_xor_sync(0xffffffffu, loy, off));
        hiy = fmaxf(hiy, __shfl_xor_sync(0xffffffffu, hiy, off));
        loz = fminf(loz, __shfl_xor_sync(0xffffffffu, loz, off));
        hiz = fmaxf(hiz, __shfl_xor_sync(0xffffffffu, hiz, off));
    }

    // warp-cached packed record: (valbits << 32) | (0xFFFFFFFF - si)
    unsigned long long rkey =
        (((unsigned long long)__float_as_uint(CUDART_INF_F)) << 32) |
        (unsigned)(0xFFFFFFFFu - (unsigned)(wid * 32 * PTS));

    // initial center = original point 0 (registers, warp-uniform broadcast LDS)
    int j0 = s_misc[0];
    int fidx0 = pair_fidx<LOGP>(j0 >> LOGP, j0 & (PTS - 1));
    float ccx = px[fidx0], ccy = py[fidx0], ccz = pz[fidx0];
    if (t == 0) sel[0] = j0;

    // ---- phase 5: the FPS scan (ONE barrier per step, atomic-key reduce) ----
    for (int step = 1; step < M; ++step) {
        int slot = step % 3;

        // warp-uniform AABB lower bound vs warp cached best: uniform branch
        float ax = fmaxf(fmaxf(lox - ccx, ccx - hix), 0.0f);
        float ay = fmaxf(fmaxf(loy - ccy, ccy - hiy), 0.0f);
        float az = fmaxf(fmaxf(loz - ccz, ccz - hiz), 0.0f);
        float lb = fmaf(ax, ax, fmaf(ay, ay, az * az)) * 0.9999f;

        if (lb < __uint_as_float((unsigned)(rkey >> 32))) {
            unsigned long long ncx2 = pk2(-ccx, -ccx);
            unsigned long long ncy2 = pk2(-ccy, -ccy);
            unsigned long long ncz2 = pk2(-ccz, -ccz);
            float bv = -CUDART_INF_F;
#pragma unroll
            for (int k2 = 0; k2 < PTS / 2; k2++) {
                int base = k2 * (2 * FPS_T) + 2 * t;
                unsigned long long X = *(const unsigned long long*)(px + base);
                unsigned long long Y = *(const unsigned long long*)(py + base);
                unsigned long long Z = *(const unsigned long long*)(pz + base);
                unsigned long long dX = add2(X, ncx2);
                unsigned long long dY = add2(Y, ncy2);
                unsigned long long dZ = add2(Z, ncz2);
                unsigned long long s2 = add2(add2(mul2(dX, dX), mul2(dY, dY)), mul2(dZ, dZ));
                float d2a, d2b;
                unpk2(s2, d2a, d2b);
                float mna = fminf(mind[2 * k2], d2a);
                mind[2 * k2] = mna;
                float mnb = fminf(mind[2 * k2 + 1], d2b);
                mind[2 * k2 + 1] = mnb;
                bv = fmaxf(bv, fmaxf(mna, mnb));
            }
            unsigned msk = 0u;
#pragma unroll
            for (int k = 0; k < PTS; k++)
                if (mind[k] == bv) msk |= (1u << k);
            int csi = t * PTS + (__ffs(msk) - 1);

            unsigned mybits = __float_as_uint(bv);
            unsigned wmax = __reduce_max_sync(0xffffffffu, mybits);
            unsigned who = __ballot_sync(0xffffffffu, mybits == wmax);
            int src = __ffs(who) - 1;
            int wsi = __shfl_sync(0xffffffffu, csi, src);
            rkey = (((unsigned long long)wmax) << 32) |
                   (unsigned)(0xFFFFFFFFu - (unsigned)wsi);
        }
        if (lane == 0) atomicMax(&s_key[slot], rkey);
        __syncthreads();   // the ONLY barrier in the step

        unsigned long long kk = s_key[slot];   // broadcast LDS.64
        int si = (int)(0xFFFFFFFFu - (unsigned)kk);
        int fidx = pair_fidx<LOGP>(si >> LOGP, si & (PTS - 1));
        ccx = px[fidx]; ccy = py[fidx]; ccz = pz[fidx];
        if (t == 0) {
            sel[step] = si;
            s_key[(step + 2) % 3] = 0ull;   // reset the slot read last step
        }
    }

    // ---- phase 6: remap raw sorted indices to original indices ----
    __syncthreads();
    for (int i = t; i < M; i += FPS_T) {
        int si_ = sel[i];
        sel[i] = sori[si_];
    }
}

// ---------------- gather sampled positions ----------------
__global__ void gather_kernel(const float4* __restrict__ src, const int* __restrict__ sel,
                              float4* __restrict__ dst, int m) {
    int i = blockIdx.x * blockDim.x + threadIdx.x;
    if (i < m) dst[i] = src[sel[i]];
}

// ---------------- SA: radius group + PointConv + max-agg ----------------
template <int NSRC>
__global__ void sa_conv_kernel(const float4* __restrict__ p4s, const float4* __restrict__ p4t,
                               const float4* __restrict__ hs, float4* __restrict__ xt,
                               const float* __restrict__ W0, const float* __restrict__ b0,
                               const float* __restrict__ W1, const float* __restrict__ b1,
                               int ntgt) {
    __shared__ float sW0[19 * 19], sW1[19 * 16], sb0[19], sb1[16];
    int t = threadIdx.x;
    for (int i = t; i < 361; i += blockDim.x) sW0[i] = W0[i];
    for (int i = t; i < 304; i += blockDim.x) sW1[i] = W1[i];
    if (t < 19) sb0[t] = b0[t];
    if (t < 16) sb1[t] = b1[t];
    __syncthreads();

    int warp = (blockIdx.x * blockDim.x + t) >> 5;
    int lane = t & 31;
    if (warp >= ntgt) return;

    float4 pt = p4t[warp];
    float na = pt.w;
    float myd = 0.0f;
    int myj = 0;
    int cnt = 0;

    for (int base = 0; base < NSRC; base += 32) {
        int j = base + lane;
        float4 ps = p4s[j];
        float dot = fmaf(pt.x, ps.x, fmaf(pt.y, ps.y, pt.z * ps.z));
        float d2 = fmaxf((na + ps.w) - 2.0f * dot, 0.0f);
        bool hit = d2 <= R2C;
        unsigned mm = __ballot_sync(0xffffffffu, hit);
        while (mm) {
            int b = __ffs(mm) - 1;
            mm &= mm - 1;
            float nd = __shfl_sync(0xffffffffu, d2, b);
            int nj = base + b;
            if (cnt < 32) {
                if (lane == cnt) { myd = nd; myj = nj; }
                cnt++;
            } else {
                float mv = (lane < cnt) ? myd : -CUDART_INF_F;
                int ml = lane;
#pragma unroll
                for (int off = 16; off; off >>= 1) {
                    float ov = __shfl_xor_sync(0xffffffffu, mv, off);
                    int ol = __shfl_xor_sync(0xffffffffu, ml, off);
                    if (ov > mv) { mv = ov; ml = ol; }
                }
                if (nd < mv && lane == ml) { myd = nd; myj = nj; }
            }
        }
    }

    bool valid = lane < cnt;
    int jj = valid ? myj : 0;
    float in[19];
    load16(&hs[jj * 4], in);
    float4 sp = p4s[jj];
    in[16] = sp.x - pt.x;
    in[17] = sp.y - pt.y;
    in[18] = sp.z - pt.z;

    float hid[19];
#pragma unroll
    for (int o = 0; o < 19; o++) hid[o] = sb0[o];
#pragma unroll
    for (int i = 0; i < 19; i++) {
        float v = in[i];
#pragma unroll
        for (int o = 0; o < 19; o++) hid[o] = fmaf(v, sW0[i * 19 + o], hid[o]);
    }
#pragma unroll
    for (int o = 0; o < 19; o++) hid[o] = fmaxf(hid[o], 0.0f);

    float out[16];
#pragma unroll
    for (int o = 0; o < 16; o++) out[o] = sb1[o];
#pragma unroll
    for (int i = 0; i < 19; i++) {
        float v = hid[i];
#pragma unroll
        for (int o = 0; o < 16; o++) out[o] = fmaf(v, sW1[i * 16 + o], out[o]);
    }
    float res[16];
#pragma unroll
    for (int c = 0; c < 16; c++) {
        float r = valid ? fmaxf(out[c], 0.0f) : -CUDART_INF_F;
#pragma unroll
        for (int off = 16; off; off >>= 1) r = fmaxf(r, __shfl_xor_sync(0xffffffffu, r, off));
        res[c] = r;
    }
    if (lane == 0) store16(&xt[warp * 4], res);
}

// ---------------- FP: kNN(3) interpolate + MLP(32->32->16) ----------------
template <int NC>
__global__ void fp_kernel(const float4* __restrict__ p4f, const float4* __restrict__ p4c,
                          const float4* __restrict__ xc, const float4* __restrict__ xs,
                          float4* __restrict__ xf,
                          const float* __restrict__ W0, const float* __restrict__ b0,
                          const float* __restrict__ W1, const float* __restrict__ b1,
                          int nf) {
    __shared__ float sW0[32 * 32], sW1[32 * 16], sb0[32], sb1[16];
    int t = threadIdx.x;
    for (int i = t; i < 1024; i += blockDim.x) sW0[i] = W0[i];
    for (int i = t; i < 512; i += blockDim.x) sW1[i] = W1[i];
    if (t < 32) sb0[t] = b0[t];
    if (t < 16) sb1[t] = b1[t];
    __syncthreads();

    int g = blockIdx.x * blockDim.x + t;
    if (g >= nf) return;
    float4 f = p4f[g];
    float na = f.w;
    float d0 = CUDART_INF_F, d1 = CUDART_INF_F, d2 = CUDART_INF_F;
    int i0 = 0, i1 = 0, i2 = 0;
    for (int j = 0; j < NC; j++) {
        float4 c = p4c[j];
        float dot = fmaf(f.x, c.x, fmaf(f.y, c.y, f.z * c.z));
        float dd = fmaxf((na + c.w) - 2.0f * dot, 0.0f);
        if (dd < d0) {
            d2 = d1; i2 = i1; d1 = d0; i1 = i0; d0 = dd; i0 = j;
        } else if (dd < d1) {
            d2 = d1; i2 = i1; d1 = dd; i1 = j;
        } else if (dd < d2) {
            d2 = dd; i2 = j;
        }
    }
    float w0 = 1.0f / fmaxf(d0, 1e-16f);
    float w1 = 1.0f / fmaxf(d1, 1e-16f);
    float w2 = 1.0f / fmaxf(d2, 1e-16f);
    float ws = w0 + w1 + w2;
    w0 /= ws; w1 /= ws; w2 /= ws;

    float a0[16], a1[16], a2[16], in[32];
    load16(&xc[i0 * 4], a0);
    load16(&xc[i1 * 4], a1);
    load16(&xc[i2 * 4], a2);
#pragma unroll
    for (int c = 0; c < 16; c++) in[c] = (a0[c] * w0 + a1[c] * w1) + a2[c] * w2;
    load16(&xs[g * 4], in + 16);

    float hid[32];
#pragma unroll
    for (int o = 0; o < 32; o++) hid[o] = sb0[o];
#pragma unroll
    for (int i = 0; i < 32; i++) {
        float v = in[i];
#pragma unroll
        for (int o = 0; o < 32; o++) hid[o] = fmaf(v, sW0[i * 32 + o], hid[o]);
    }
#pragma unroll
    for (int o = 0; o < 32; o++) hid[o] = fmaxf(hid[o], 0.0f);
    float out[16];
#pragma unroll
    for (int o = 0; o < 16; o++) out[o] = sb1[o];
#pragma unroll
    for (int i = 0; i < 32; i++) {
        float v = hid[i];
#pragma unroll
        for (int o = 0; o < 16; o++) out[o] = fmaf(v, sW1[i * 16 + o], out[o]);
    }
#pragma unroll
    for (int o = 0; o < 16; o++) out[o] = fmaxf(out[o], 0.0f);
    store16(&xf[g * 4], out);
}

// ---------------- lin_out ----------------
__global__ void lin_out_kernel(const float* __restrict__ W0, const float* __restrict__ b0,
                               const float* __restrict__ W1, const float* __restrict__ b1,
                               float* __restrict__ out) {
    __shared__ float sW0[256], sW1[32], sb0[16], sb1[2];
    int t = threadIdx.x;
    for (int i = t; i < 256; i += blockDim.x) sW0[i] = W0[i];
    if (t < 32) sW1[t] = W1[t];
    if (t < 16) sb0[t] = b0[t];
    if (t < 2) sb1[t] = b1[t];
    __syncthreads();
    int g = blockIdx.x * blockDim.x + t;
    if (g >= N0) return;
    float in[16], hid[16];
    load16(&g_f0[g * 4], in);
#pragma unroll
    for (int o = 0; o < 16; o++) hid[o] = sb0[o];
#pragma unroll
    for (int i = 0; i < 16; i++) {
        float v = in[i];
#pragma unroll
        for (int o = 0; o < 16; o++) hid[o] = fmaf(v, sW0[i * 16 + o], hid[o]);
    }
    float o0 = sb1[0], o1 = sb1[1];
#pragma unroll
    for (int i = 0; i < 16; i++) {
        float v = fmaxf(hid[i], 0.0f);
        o0 = fmaf(v, sW1[i * 2 + 0], o0);
        o1 = fmaf(v, sW1[i * 2 + 1], o1);
    }
    out[g * 2 + 0] = o0;
    out[g * 2 + 1] = o1;
}

// ---------------- host launcher ----------------
extern "C" void kernel_launch(void* const* d_in, const int* in_sizes, int n_in,
                              void* d_out, int out_size) {
    const float* x = (const float*)d_in[0];
    const float* pos = (const float*)d_in[1];
    const float* liW0 = (const float*)d_in[3];
    const float* lib0 = (const float*)d_in[4];
    const float* liW1 = (const float*)d_in[5];
    const float* lib1 = (const float*)d_in[6];
    const float* saW0 = (const float*)d_in[7];
    const float* sab0 = (const float*)d_in[8];
    const float* saW1 = (const float*)d_in[9];
    const float* sab1 = (const float*)d_in[10];
    const float* fpW0 = (const float*)d_in[11];
    const float* fpb0 = (const float*)d_in[12];
    const float* fpW1 = (const float*)d_in[13];
    const float* fpb1 = (const float*)d_in[14];
    const float* loW0 = (const float*)d_in[15];
    const float* lob0 = (const float*)d_in[16];
    const float* loW1 = (const float*)d_in[17];
    const float* lob1 = (const float*)d_in[18];
    float* out = (float*)d_out;

    void *p40, *p41, *p42, *p43, *s0, *s1, *s2, *sori, *h0, *x1, *x2, *x3, *f2, *f1, *f0;
    cudaGetSymbolAddress(&p40, g_p4_0);
    cudaGetSymbolAddress(&p41, g_p4_1);
    cudaGetSymbolAddress(&p42, g_p4_2);
    cudaGetSymbolAddress(&p43, g_p4_3);
    cudaGetSymbolAddress(&s0, g_sel0);
    cudaGetSymbolAddress(&s1, g_sel1);
    cudaGetSymbolAddress(&s2, g_sel2);
    cudaGetSymbolAddress(&sori, g_sori);
    cudaGetSymbolAddress(&h0, g_h0);
    cudaGetSymbolAddress(&x1, g_x1);
    cudaGetSymbolAddress(&x2, g_x2);
    cudaGetSymbolAddress(&x3, g_x3);
    cudaGetSymbolAddress(&f2, g_f2);
    cudaGetSymbolAddress(&f1, g_f1);
    cudaGetSymbolAddress(&f0, g_f0);

    size_t sm0 = (size_t)N0 * 12;
    size_t sm1 = (size_t)N1 * 12;
    size_t sm2 = (size_t)N2 * 12;
    cudaFuncSetAttribute((const void*)fps_kernel<N0, N1, 16, 4>,
                         cudaFuncAttributeMaxDynamicSharedMemorySize, (int)sm0);
    cudaFuncSetAttribute((const void*)fps_kernel<N1, N2, 8, 3>,
                         cudaFuncAttributeMaxDynamicSharedMemorySize, (int)sm1);
    cudaFuncSetAttribute((const void*)fps_kernel<N2, N3, 4, 3>,
                         cudaFuncAttributeMaxDynamicSharedMemorySize, (int)sm2);

    prep_kernel<<<(N0 + 255) / 256, 256>>>(pos);
    warm_kernel<<<1, 32>>>();
    lin_in_kernel<<<N0 / 128, 128>>>(x, liW0, lib0, liW1, lib1);

    // level 0
    fps_kernel<N0, N1, 16, 4><<<1, FPS_T, sm0>>>((const float4*)p40, (int*)s0, (int*)sori);
    gather_kernel<<<N1 / 256, 256>>>((const float4*)p40, (const int*)s0, (float4*)p41, N1);
    sa_conv_kernel<N0><<<N1 * 32 / 256, 256>>>((const float4*)p40, (const float4*)p41,
                                               (const float4*)h0, (float4*)x1,
                                               saW0, sab0, saW1, sab1, N1);
    // level 1
    fps_kernel<N1, N2, 8, 3><<<1, FPS_T, sm1>>>((const float4*)p41, (int*)s1, (int*)sori);
    gather_kernel<<<N2 / 256, 256>>>((const float4*)p41, (const int*)s1, (float4*)p42, N2);
    sa_conv_kernel<N1><<<N2 * 32 / 256, 256>>>((const float4*)p41, (const float4*)p42,
                                               (const float4*)x1, (float4*)x2,
                                               saW0 + 361, sab0 + 19, saW1 + 304, sab1 + 16, N2);
    // level 2
    fps_kernel<N2, N3, 4, 3><<<1, FPS_T, sm2>>>((const float4*)p42, (int*)s2, (int*)sori);
    gather_kernel<<<N3 / 256, 256>>>((const float4*)p42, (const int*)s2, (float4*)p43, N3);
    sa_conv_kernel<N2><<<N3 * 32 / 256, 256>>>((const float4*)p42, (const float4*)p43,
                                               (const float4*)x2, (float4*)x3,
                                               saW0 + 722, sab0 + 38, saW1 + 608, sab1 + 32, N3);

    // FP path (coarse -> fine)
    fp_kernel<N3><<<N2 / 128, 128>>>((const float4*)p42, (const float4*)p43,
                                     (const float4*)x3, (const float4*)x2, (float4*)f2,
                                     fpW0 + 2 * 1024, fpb0 + 2 * 32, fpW1 + 2 * 512, fpb1 + 2 * 16,
                                     N2);
    fp_kernel<N2><<<N1 / 128, 128>>>((const float4*)p41, (const float4*)p42,
                                     (const float4*)f2, (const float4*)x1, (float4*)f1,
                                     fpW0 + 1024, fpb0 + 32, fpW1 + 512, fpb1 + 16, N1);
    fp_kernel<N1><<<N0 / 128, 128>>>((const float4*)p40, (const float4*)p41,
                                     (const float4*)f1, (const float4*)h0, (float4*)f0,
                                     fpW0, fpb0, fpW1, fpb1, N0);

    lin_out_kernel<<<N0 / 256, 256>>>(loW0, lob0, loW1, lob1, out);
}

// round 13
// speedup vs baseline: 1.0500x; 1.0500x over previous
#include <cuda_runtime.h>
#include <math_constants.h>

#define N0 16384
#define N1 8192
#define N2 4096
#define N3 2048
#define R2C 4.0f
#define FPS_T 1024

// ---------------- device scratch (no allocations allowed) ----------------
__device__ float4 g_p4_0[N0];
__device__ float4 g_p4_1[N1];
__device__ float4 g_p4_2[N2];
__device__ float4 g_p4_3[N3];
__device__ int    g_sel0[N1];
__device__ int    g_sel1[N2];
__device__ int    g_sel2[N3];
__device__ int    g_sori[N0];     // per-level sorted->original index scratch
__device__ float4 g_h0[N0 * 4];   // 16 floats per point
__device__ float4 g_x1[N1 * 4];
__device__ float4 g_x2[N2 * 4];
__device__ float4 g_x3[N3 * 4];
__device__ float4 g_f2[N2 * 4];
__device__ float4 g_f1[N1 * 4];
__device__ float4 g_f0[N0 * 4];

// ---------------- packed f32x2 helpers (component-wise IEEE rn, identical to scalar) ----
__device__ __forceinline__ unsigned long long pk2(float lo, float hi) {
    unsigned long long r;
    asm("mov.b64 %0, {%1, %2};" : "=l"(r) : "f"(lo), "f"(hi));
    return r;
}
__device__ __forceinline__ void unpk2(unsigned long long v, float& lo, float& hi) {
    asm("mov.b64 {%0, %1}, %2;" : "=f"(lo), "=f"(hi) : "l"(v));
}
__device__ __forceinline__ unsigned long long add2(unsigned long long a, unsigned long long b) {
    unsigned long long r;
    asm("add.rn.f32x2 %0, %1, %2;" : "=l"(r) : "l"(a), "l"(b));
    return r;
}
__device__ __forceinline__ unsigned long long mul2(unsigned long long a, unsigned long long b) {
    unsigned long long r;
    asm("mul.rn.f32x2 %0, %1, %2;" : "=l"(r) : "l"(a), "l"(b));
    return r;
}

// ---------------- prep: pack pos + squared norm into float4 ----------------
__global__ void prep_kernel(const float* __restrict__ pos) {
    int i = blockIdx.x * blockDim.x + threadIdx.x;
    if (i >= N0) return;
    float x = pos[3 * i], y = pos[3 * i + 1], z = pos[3 * i + 2];
    float nb = __fadd_rn(__fadd_rn(__fmul_rn(x, x), __fmul_rn(y, y)), __fmul_rn(z, z));
    g_p4_0[i] = make_float4(x, y, z, nb);
}

// no-op kernel: shifts launch indices so the ncu capture slot lands on fps0
__global__ void warm_kernel() {}

__device__ __forceinline__ void load16(const float4* __restrict__ row, float* v) {
    float4 a = row[0], b = row[1], c = row[2], d = row[3];
    v[0] = a.x; v[1] = a.y; v[2] = a.z; v[3] = a.w;
    v[4] = b.x; v[5] = b.y; v[6] = b.z; v[7] = b.w;
    v[8] = c.x; v[9] = c.y; v[10] = c.z; v[11] = c.w;
    v[12] = d.x; v[13] = d.y; v[14] = d.z; v[15] = d.w;
}

__device__ __forceinline__ void store16(float4* __restrict__ row, const float* v) {
    row[0] = make_float4(v[0], v[1], v[2], v[3]);
    row[1] = make_float4(v[4], v[5], v[6], v[7]);
    row[2] = make_float4(v[8], v[9], v[10], v[11]);
    row[3] = make_float4(v[12], v[13], v[14], v[15]);
}

// ---------------- lin_in ----------------
__global__ void lin_in_kernel(const float* __restrict__ x,
                              const float* __restrict__ W0, const float* __restrict__ b0,
                              const float* __restrict__ W1, const float* __restrict__ b1) {
    __shared__ float sW0[256], sW1[256], sb0[16], sb1[16];
    int t = threadIdx.x;
    for (int i = t; i < 256; i += blockDim.x) { sW0[i] = W0[i]; sW1[i] = W1[i]; }
    if (t < 16) { sb0[t] = b0[t]; sb1[t] = b1[t]; }
    __syncthreads();
    int g = blockIdx.x * blockDim.x + t;
    if (g >= N0) return;
    float in[16], hid[16], out[16];
    load16((const float4*)(x + g * 16), in);
#pragma unroll
    for (int o = 0; o < 16; o++) hid[o] = sb0[o];
#pragma unroll
    for (int i = 0; i < 16; i++) {
        float v = in[i];
#pragma unroll
        for (int o = 0; o < 16; o++) hid[o] = fmaf(v, sW0[i * 16 + o], hid[o]);
    }
#pragma unroll
    for (int o = 0; o < 16; o++) hid[o] = fmaxf(hid[o], 0.0f);
#pragma unroll
    for (int o = 0; o < 16; o++) out[o] = sb1[o];
#pragma unroll
    for (int i = 0; i < 16; i++) {
        float v = hid[i];
#pragma unroll
        for (int o = 0; o < 16; o++) out[o] = fmaf(v, sW1[i * 16 + o], out[o]);
    }
#pragma unroll
    for (int o = 0; o < 16; o++) out[o] = fmaxf(out[o], 0.0f);
    store16(&g_h0[g * 4], out);
}

// ---------------- FPS: spatial sort + warp-AABB pruning + two-barrier leader ----------
template <int GB>
__device__ __forceinline__ int mcell(float x, float y, float z) {
    const float inv = (float)(1 << GB) * (1.0f / 32.0f);
    int cx = min((1 << GB) - 1, max(0, (int)(x * inv)));
    int cy = min((1 << GB) - 1, max(0, (int)(y * inv)));
    int cz = min((1 << GB) - 1, max(0, (int)(z * inv)));
    int m = 0;
#pragma unroll
    for (int b = 0; b < GB; b++)
        m |= (((cx >> b) & 1) << (3 * b)) | (((cy >> b) & 1) << (3 * b + 1)) |
             (((cz >> b) & 1) << (3 * b + 2));
    return m;
}

// pair-interleaved float index for sorted point (thread tt, chunk slot kk)
template <int LOGP>
__device__ __forceinline__ int pair_fidx(int tt, int kk) {
    return (kk >> 1) * (2 * FPS_T) + 2 * tt + (kk & 1);
}

// NPTS points, select M, PTS = NPTS/1024 points per thread, GB grid bits per dim
template <int NPTS, int M, int PTS, int GB>
__global__ __launch_bounds__(FPS_T, 1)
void fps_kernel(const float4* __restrict__ p4, int* __restrict__ sel, int* __restrict__ sori) {
    constexpr int NCELL = 1 << (3 * GB);
    constexpr int LOGP = (PTS == 16) ? 4 : (PTS == 8) ? 3 : 2;
    __shared__ int s_hist[4096];
    __shared__ unsigned s_val[32];              // persistent per-warp best value bits
    __shared__ __align__(16) float4 s_ctr[32];  // persistent per-warp (cx,cy,cz,si)
    __shared__ __align__(16) float4 s_ctrv;     // published winner (cx,cy,cz,si)
    __shared__ int s_misc[40];

    extern __shared__ float sm[];
    float* px = sm;
    float* py = sm + NPTS;
    float* pz = sm + 2 * NPTS;

    const int t = threadIdx.x;
    const int lane = t & 31;
    const int wid = t >> 5;

    // ---- phase 1: histogram ----
    for (int i = t; i < NCELL; i += FPS_T) s_hist[i] = 0;
    __syncthreads();
    for (int i = t; i < NPTS; i += FPS_T) {
        float4 p = p4[i];
        atomicAdd(&s_hist[mcell<GB>(p.x, p.y, p.z)], 1);
    }
    __syncthreads();

    // ---- phase 2: exclusive block scan of s_hist[0..NCELL) ----
    {
        constexpr int PER = (NCELL + FPS_T - 1) / FPS_T;
        int base = t * PER;
        int vals[PER];
        int run = 0;
#pragma unroll
        for (int q = 0; q < PER; q++) {
            int v = (base + q < NCELL) ? s_hist[base + q] : 0;
            vals[q] = v;
            run += v;
        }
        int inc = run;
#pragma unroll
        for (int off = 1; off < 32; off <<= 1) {
            int nb = __shfl_up_sync(0xffffffffu, inc, off);
            if (lane >= off) inc += nb;
        }
        if (lane == 31) s_misc[8 + wid] = inc;
        __syncthreads();
        if (t < 32) {
            int w = s_misc[8 + t];
            int winc = w;
#pragma unroll
            for (int off = 1; off < 32; off <<= 1) {
                int nb = __shfl_up_sync(0xffffffffu, winc, off);
                if (t >= off) winc += nb;
            }
            s_misc[8 + t] = winc - w;
        }
        __syncthreads();
        int off0 = s_misc[8 + wid] + (inc - run);
#pragma unroll
        for (int q = 0; q < PER; q++) {
            if (base + q < NCELL) s_hist[base + q] = off0;
            off0 += vals[q];
        }
    }
    __syncthreads();

    // ---- phase 3: scatter into pair-interleaved smem layout ----
    for (int i = t; i < NPTS; i += FPS_T) {
        float4 p = p4[i];
        int d = atomicAdd(&s_hist[mcell<GB>(p.x, p.y, p.z)], 1);
        int tt = d >> LOGP;
        int kk = d & (PTS - 1);
        int fidx = pair_fidx<LOGP>(tt, kk);
        px[fidx] = p.x; py[fidx] = p.y; pz[fidx] = p.z;
        sori[d] = i;
        if (i == 0) s_misc[0] = d;
    }
    __syncthreads();

    // ---- phase 4: per-thread mind init + WARP-level AABB ----
    float mind[PTS];
    float lox = CUDART_INF_F, loy = CUDART_INF_F, loz = CUDART_INF_F;
    float hix = -CUDART_INF_F, hiy = -CUDART_INF_F, hiz = -CUDART_INF_F;
#pragma unroll
    for (int k = 0; k < PTS; k++) {
        int fidx = pair_fidx<LOGP>(t, k);
        float X = px[fidx], Y = py[fidx], Z = pz[fidx];
        lox = fminf(lox, X); hix = fmaxf(hix, X);
        loy = fminf(loy, Y); hiy = fmaxf(hiy, Y);
        loz = fminf(loz, Z); hiz = fmaxf(hiz, Z);
        mind[k] = CUDART_INF_F;
    }
#pragma unroll
    for (int off = 16; off; off >>= 1) {
        lox = fminf(lox, __shfl_xor_sync(0xffffffffu, lox, off));
        hix = fmaxf(hix, __shfl_xor_sync(0xffffffffu, hix, off));
        loy = fminf(loy, __shfl_xor_sync(0xffffffffu, loy, off));
        hiy = fmaxf(hiy, __shfl_xor_sync(0xffffffffu, hiy, off));
        loz = fminf(loz, __shfl_xor_sync(0xffffffffu, loz, off));
        hiz = fmaxf(hiz, __shfl_xor_sync(0xffffffffu, hiz, off));
    }

    float wbest = CUDART_INF_F;   // warp-uniform cached best (REDUX result)
    if (lane == 0) {
        s_val[wid] = __float_as_uint(CUDART_INF_F);
        s_ctr[wid] = make_float4(0.0f, 0.0f, 0.0f, __int_as_float(wid * 32 * PTS));
    }

    // prologue: publish the first center (original point 0)
    if (wid == 0) {
        int j0 = s_misc[0];
        int fidx = pair_fidx<LOGP>(j0 >> LOGP, j0 & (PTS - 1));
        if (lane == 0) {
            s_ctrv = make_float4(px[fidx], py[fidx], pz[fidx], __int_as_float(j0));
            sel[0] = j0;
        }
    }
    __syncthreads();

    // ---- phase 5: the FPS scan ----
    for (int step = 1; step < M; ++step) {
        float4 c = s_ctrv;   // one broadcast LDS.128 per warp
        float ccx = c.x, ccy = c.y, ccz = c.z;

        float ax = fmaxf(fmaxf(lox - ccx, ccx - hix), 0.0f);
        float ay = fmaxf(fmaxf(loy - ccy, ccy - hiy), 0.0f);
        float az = fmaxf(fmaxf(loz - ccz, ccz - hiz), 0.0f);
        float lb = fmaf(ax, ax, fmaf(ay, ay, az * az)) * 0.9999f;

        if (lb < wbest) {
            unsigned long long ncx2 = pk2(-ccx, -ccx);
            unsigned long long ncy2 = pk2(-ccy, -ccy);
            unsigned long long ncz2 = pk2(-ccz, -ccz);
            float bv = -CUDART_INF_F;
#pragma unroll
            for (int k2 = 0; k2 < PTS / 2; k2++) {
                int base = k2 * (2 * FPS_T) + 2 * t;
                unsigned long long X = *(const unsigned long long*)(px + base);
                unsigned long long Y = *(const unsigned long long*)(py + base);
                unsigned long long Z = *(const unsigned long long*)(pz + base);
                unsigned long long dX = add2(X, ncx2);
                unsigned long long dY = add2(Y, ncy2);
                unsigned long long dZ = add2(Z, ncz2);
                unsigned long long s2 = add2(add2(mul2(dX, dX), mul2(dY, dY)), mul2(dZ, dZ));
                float d2a, d2b;
                unpk2(s2, d2a, d2b);
                float mna = fminf(mind[2 * k2], d2a);
                mind[2 * k2] = mna;
                float mnb = fminf(mind[2 * k2 + 1], d2b);
                mind[2 * k2 + 1] = mnb;
                bv = fmaxf(bv, fmaxf(mna, mnb));
            }
            unsigned msk = 0u;
#pragma unroll
            for (int k = 0; k < PTS; k++)
                if (mind[k] == bv) msk |= (1u << k);
            int csi = t * PTS + (__ffs(msk) - 1);

            unsigned mybits = __float_as_uint(bv);
            unsigned wmax = __reduce_max_sync(0xffffffffu, mybits);
            unsigned who = __ballot_sync(0xffffffffu, mybits == wmax);
            int src = __ffs(who) - 1;
            int wsi = __shfl_sync(0xffffffffu, csi, src);
            wbest = __uint_as_float(wmax);
            // fetch candidate coordinates HERE (parallel across touched warps,
            // off the leader's serial chain)
            int fidx = pair_fidx<LOGP>(wsi >> LOGP, wsi & (PTS - 1));
            float wx = px[fidx], wy = py[fidx], wz = pz[fidx];
            if (lane == 0) {
                s_val[wid] = wmax;
                s_ctr[wid] = make_float4(wx, wy, wz, __int_as_float(wsi));
            }
        }
        __syncthreads();   // bar1: per-warp bests + candidate coords visible

        if (wid == 0) {
            // leader: short serial chain, no coordinate gather
            unsigned v = s_val[lane];
            unsigned bmax = __reduce_max_sync(0xffffffffu, v);
            unsigned wwin = __ballot_sync(0xffffffffu, v == bmax);
            int widwin = __ffs(wwin) - 1;
            if (lane == 0) s_ctrv = s_ctr[widwin];   // LDS.128 + STS.128
        }
        __syncthreads();   // bar2: new center visible

        if (t == 0) sel[step] = __float_as_int(s_ctrv.w);   // off-chain STG
    }

    // ---- phase 6: remap raw sorted indices to original indices ----
    __syncthreads();
    for (int i = t; i < M; i += FPS_T) {
        int si_ = sel[i];
        sel[i] = sori[si_];
    }
}

// ---------------- gather sampled positions ----------------
__global__ void gather_kernel(const float4* __restrict__ src, const int* __restrict__ sel,
                              float4* __restrict__ dst, int m) {
    int i = blockIdx.x * blockDim.x + threadIdx.x;
    if (i < m) dst[i] = src[sel[i]];
}

// ---------------- SA: radius group + PointConv + max-agg ----------------
template <int NSRC>
__global__ void sa_conv_kernel(const float4* __restrict__ p4s, const float4* __restrict__ p4t,
                               const float4* __restrict__ hs, float4* __restrict__ xt,
                               const float* __restrict__ W0, const float* __restrict__ b0,
                               const float* __restrict__ W1, const float* __restrict__ b1,
                               int ntgt) {
    __shared__ float sW0[19 * 19], sW1[19 * 16], sb0[19], sb1[16];
    int t = threadIdx.x;
    for (int i = t; i < 361; i += blockDim.x) sW0[i] = W0[i];
    for (int i = t; i < 304; i += blockDim.x) sW1[i] = W1[i];
    if (t < 19) sb0[t] = b0[t];
    if (t < 16) sb1[t] = b1[t];
    __syncthreads();

    int warp = (blockIdx.x * blockDim.x + t) >> 5;
    int lane = t & 31;
    if (warp >= ntgt) return;

    float4 pt = p4t[warp];
    float na = pt.w;
    float myd = 0.0f;
    int myj = 0;
    int cnt = 0;

    for (int base = 0; base < NSRC; base += 32) {
        int j = base + lane;
        float4 ps = p4s[j];
        float dot = fmaf(pt.x, ps.x, fmaf(pt.y, ps.y, pt.z * ps.z));
        float d2 = fmaxf((na + ps.w) - 2.0f * dot, 0.0f);
        bool hit = d2 <= R2C;
        unsigned mm = __ballot_sync(0xffffffffu, hit);
        while (mm) {
            int b = __ffs(mm) - 1;
            mm &= mm - 1;
            float nd = __shfl_sync(0xffffffffu, d2, b);
            int nj = base + b;
            if (cnt < 32) {
                if (lane == cnt) { myd = nd; myj = nj; }
                cnt++;
            } else {
                float mv = (lane < cnt) ? myd : -CUDART_INF_F;
                int ml = lane;
#pragma unroll
                for (int off = 16; off; off >>= 1) {
                    float ov = __shfl_xor_sync(0xffffffffu, mv, off);
                    int ol = __shfl_xor_sync(0xffffffffu, ml, off);
                    if (ov > mv) { mv = ov; ml = ol; }
                }
                if (nd < mv && lane == ml) { myd = nd; myj = nj; }
            }
        }
    }

    bool valid = lane < cnt;
    int jj = valid ? myj : 0;
    float in[19];
    load16(&hs[jj * 4], in);
    float4 sp = p4s[jj];
    in[16] = sp.x - pt.x;
    in[17] = sp.y - pt.y;
    in[18] = sp.z - pt.z;

    float hid[19];
#pragma unroll
    for (int o = 0; o < 19; o++) hid[o] = sb0[o];
#pragma unroll
    for (int i = 0; i < 19; i++) {
        float v = in[i];
#pragma unroll
        for (int o = 0; o < 19; o++) hid[o] = fmaf(v, sW0[i * 19 + o], hid[o]);
    }
#pragma unroll
    for (int o = 0; o < 19; o++) hid[o] = fmaxf(hid[o], 0.0f);

    float out[16];
#pragma unroll
    for (int o = 0; o < 16; o++) out[o] = sb1[o];
#pragma unroll
    for (int i = 0; i < 19; i++) {
        float v = hid[i];
#pragma unroll
        for (int o = 0; o < 16; o++) out[o] = fmaf(v, sW1[i * 16 + o], out[o]);
    }
    float res[16];
#pragma unroll
    for (int c = 0; c < 16; c++) {
        float r = valid ? fmaxf(out[c], 0.0f) : -CUDART_INF_F;
#pragma unroll
        for (int off = 16; off; off >>= 1) r = fmaxf(r, __shfl_xor_sync(0xffffffffu, r, off));
        res[c] = r;
    }
    if (lane == 0) store16(&xt[warp * 4], res);
}

// ---------------- FP: kNN(3) interpolate + MLP(32->32->16) ----------------
template <int NC>
__global__ void fp_kernel(const float4* __restrict__ p4f, const float4* __restrict__ p4c,
                          const float4* __restrict__ xc, const float4* __restrict__ xs,
                          float4* __restrict__ xf,
                          const float* __restrict__ W0, const float* __restrict__ b0,
                          const float* __restrict__ W1, const float* __restrict__ b1,
                          int nf) {
    __shared__ float sW0[32 * 32], sW1[32 * 16], sb0[32], sb1[16];
    int t = threadIdx.x;
    for (int i = t; i < 1024; i += blockDim.x) sW0[i] = W0[i];
    for (int i = t; i < 512; i += blockDim.x) sW1[i] = W1[i];
    if (t < 32) sb0[t] = b0[t];
    if (t < 16) sb1[t] = b1[t];
    __syncthreads();

    int g = blockIdx.x * blockDim.x + t;
    if (g >= nf) return;
    float4 f = p4f[g];
    float na = f.w;
    float d0 = CUDART_INF_F, d1 = CUDART_INF_F, d2 = CUDART_INF_F;
    int i0 = 0, i1 = 0, i2 = 0;
    for (int j = 0; j < NC; j++) {
        float4 c = p4c[j];
        float dot = fmaf(f.x, c.x, fmaf(f.y, c.y, f.z * c.z));
        float dd = fmaxf((na + c.w) - 2.0f * dot, 0.0f);
        if (dd < d0) {
            d2 = d1; i2 = i1; d1 = d0; i1 = i0; d0 = dd; i0 = j;
        } else if (dd < d1) {
            d2 = d1; i2 = i1; d1 = dd; i1 = j;
        } else if (dd < d2) {
            d2 = dd; i2 = j;
        }
    }
    float w0 = 1.0f / fmaxf(d0, 1e-16f);
    float w1 = 1.0f / fmaxf(d1, 1e-16f);
    float w2 = 1.0f / fmaxf(d2, 1e-16f);
    float ws = w0 + w1 + w2;
    w0 /= ws; w1 /= ws; w2 /= ws;

    float a0[16], a1[16], a2[16], in[32];
    load16(&xc[i0 * 4], a0);
    load16(&xc[i1 * 4], a1);
    load16(&xc[i2 * 4], a2);
#pragma unroll
    for (int c = 0; c < 16; c++) in[c] = (a0[c] * w0 + a1[c] * w1) + a2[c] * w2;
    load16(&xs[g * 4], in + 16);

    float hid[32];
#pragma unroll
    for (int o = 0; o < 32; o++) hid[o] = sb0[o];
#pragma unroll
    for (int i = 0; i < 32; i++) {
        float v = in[i];
#pragma unroll
        for (int o = 0; o < 32; o++) hid[o] = fmaf(v, sW0[i * 32 + o], hid[o]);
    }
#pragma unroll
    for (int o = 0; o < 32; o++) hid[o] = fmaxf(hid[o], 0.0f);
    float out[16];
#pragma unroll
    for (int o = 0; o < 16; o++) out[o] = sb1[o];
#pragma unroll
    for (int i = 0; i < 32; i++) {
        float v = hid[i];
#pragma unroll
        for (int o = 0; o < 16; o++) out[o] = fmaf(v, sW1[i * 16 + o], out[o]);
    }
#pragma unroll
    for (int o = 0; o < 16; o++) out[o] = fmaxf(out[o], 0.0f);
    store16(&xf[g * 4], out);
}

// ---------------- lin_out ----------------
__global__ void lin_out_kernel(const float* __restrict__ W0, const float* __restrict__ b0,
                               const float* __restrict__ W1, const float* __restrict__ b1,
                               float* __restrict__ out) {
    __shared__ float sW0[256], sW1[32], sb0[16], sb1[2];
    int t = threadIdx.x;
    for (int i = t; i < 256; i += blockDim.x) sW0[i] = W0[i];
    if (t < 32) sW1[t] = W1[t];
    if (t < 16) sb0[t] = b0[t];
    if (t < 2) sb1[t] = b1[t];
    __syncthreads();
    int g = blockIdx.x * blockDim.x + t;
    if (g >= N0) return;
    float in[16], hid[16];
    load16(&g_f0[g * 4], in);
#pragma unroll
    for (int o = 0; o < 16; o++) hid[o] = sb0[o];
#pragma unroll
    for (int i = 0; i < 16; i++) {
        float v = in[i];
#pragma unroll
        for (int o = 0; o < 16; o++) hid[o] = fmaf(v, sW0[i * 16 + o], hid[o]);
    }
    float o0 = sb1[0], o1 = sb1[1];
#pragma unroll
    for (int i = 0; i < 16; i++) {
        float v = fmaxf(hid[i], 0.0f);
        o0 = fmaf(v, sW1[i * 2 + 0], o0);
        o1 = fmaf(v, sW1[i * 2 + 1], o1);
    }
    out[g * 2 + 0] = o0;
    out[g * 2 + 1] = o1;
}

// ---------------- host launcher ----------------
extern "C" void kernel_launch(void* const* d_in, const int* in_sizes, int n_in,
                              void* d_out, int out_size) {
    const float* x = (const float*)d_in[0];
    const float* pos = (const float*)d_in[1];
    const float* liW0 = (const float*)d_in[3];
    const float* lib0 = (const float*)d_in[4];
    const float* liW1 = (const float*)d_in[5];
    const float* lib1 = (const float*)d_in[6];
    const float* saW0 = (const float*)d_in[7];
    const float* sab0 = (const float*)d_in[8];
    const float* saW1 = (const float*)d_in[9];
    const float* sab1 = (const float*)d_in[10];
    const float* fpW0 = (const float*)d_in[11];
    const float* fpb0 = (const float*)d_in[12];
    const float* fpW1 = (const float*)d_in[13];
    const float* fpb1 = (const float*)d_in[14];
    const float* loW0 = (const float*)d_in[15];
    const float* lob0 = (const float*)d_in[16];
    const float* loW1 = (const float*)d_in[17];
    const float* lob1 = (const float*)d_in[18];
    float* out = (float*)d_out;

    void *p40, *p41, *p42, *p43, *s0, *s1, *s2, *sori, *h0, *x1, *x2, *x3, *f2, *f1, *f0;
    cudaGetSymbolAddress(&p40, g_p4_0);
    cudaGetSymbolAddress(&p41, g_p4_1);
    cudaGetSymbolAddress(&p42, g_p4_2);
    cudaGetSymbolAddress(&p43, g_p4_3);
    cudaGetSymbolAddress(&s0, g_sel0);
    cudaGetSymbolAddress(&s1, g_sel1);
    cudaGetSymbolAddress(&s2, g_sel2);
    cudaGetSymbolAddress(&sori, g_sori);
    cudaGetSymbolAddress(&h0, g_h0);
    cudaGetSymbolAddress(&x1, g_x1);
    cudaGetSymbolAddress(&x2, g_x2);
    cudaGetSymbolAddress(&x3, g_x3);
    cudaGetSymbolAddress(&f2, g_f2);
    cudaGetSymbolAddress(&f1, g_f1);
    cudaGetSymbolAddress(&f0, g_f0);

    size_t sm0 = (size_t)N0 * 12;
    size_t sm1 = (size_t)N1 * 12;
    size_t sm2 = (size_t)N2 * 12;
    cudaFuncSetAttribute((const void*)fps_kernel<N0, N1, 16, 4>,
                         cudaFuncAttributeMaxDynamicSharedMemorySize, (int)sm0);
    cudaFuncSetAttribute((const void*)fps_kernel<N1, N2, 8, 3>,
                         cudaFuncAttributeMaxDynamicSharedMemorySize, (int)sm1);
    cudaFuncSetAttribute((const void*)fps_kernel<N2, N3, 4, 3>,
                         cudaFuncAttributeMaxDynamicSharedMemorySize, (int)sm2);

    prep_kernel<<<(N0 + 255) / 256, 256>>>(pos);
    warm_kernel<<<1, 32>>>();
    lin_in_kernel<<<N0 / 128, 128>>>(x, liW0, lib0, liW1, lib1);

    // level 0
    fps_kernel<N0, N1, 16, 4><<<1, FPS_T, sm0>>>((const float4*)p40, (int*)s0, (int*)sori);
    gather_kernel<<<N1 / 256, 256>>>((const float4*)p40, (const int*)s0, (float4*)p41, N1);
    sa_conv_kernel<N0><<<N1 * 32 / 256, 256>>>((const float4*)p40, (const float4*)p41,
                                               (const float4*)h0, (float4*)x1,
                                               saW0, sab0, saW1, sab1, N1);
    // level 1
    fps_kernel<N1, N2, 8, 3><<<1, FPS_T, sm1>>>((const float4*)p41, (int*)s1, (int*)sori);
    gather_kernel<<<N2 / 256, 256>>>((const float4*)p41, (const int*)s1, (float4*)p42, N2);
    sa_conv_kernel<N1><<<N2 * 32 / 256, 256>>>((const float4*)p41, (const float4*)p42,
                                               (const float4*)x1, (float4*)x2,
                                               saW0 + 361, sab0 + 19, saW1 + 304, sab1 + 16, N2);
    // level 2
    fps_kernel<N2, N3, 4, 3><<<1, FPS_T, sm2>>>((const float4*)p42, (int*)s2, (int*)sori);
    gather_kernel<<<N3 / 256, 256>>>((const float4*)p42, (const int*)s2, (float4*)p43, N3);
    sa_conv_kernel<N2><<<N3 * 32 / 256, 256>>>((const float4*)p42, (const float4*)p43,
                                               (const float4*)x2, (float4*)x3,
                                               saW0 + 722, sab0 + 38, saW1 + 608, sab1 + 32, N3);

    // FP path (coarse -> fine)
    fp_kernel<N3><<<N2 / 128, 128>>>((const float4*)p42, (const float4*)p43,
                                     (const float4*)x3, (const float4*)x2, (float4*)f2,
                                     fpW0 + 2 * 1024, fpb0 + 2 * 32, fpW1 + 2 * 512, fpb1 + 2 * 16,
                                     N2);
    fp_kernel<N2><<<N1 / 128, 128>>>((const float4*)p41, (const float4*)p42,
                                     (const float4*)f2, (const float4*)x1, (float4*)f1,
                                     fpW0 + 1024, fpb0 + 32, fpW1 + 512, fpb1 + 16, N1);
    fp_kernel<N1><<<N0 / 128, 128>>>((const float4*)p40, (const float4*)p41,
                                     (const float4*)f1, (const float4*)h0, (float4*)f0,
                                     fpW0, fpb0, fpW1, fpb1, N0);

    lin_out_kernel<<<N0 / 256, 256>>>(loW0, lob0, loW1, lob1, out);
}

// round 14
// speedup vs baseline: 1.2099x; 1.1523x over previous
#include <cuda_runtime.h>
#include <math_constants.h>

#define N0 16384
#define N1 8192
#define N2 4096
#define N3 2048
#define R2C 4.0f
#define FPS_T 1024

// ---------------- device scratch (no allocations allowed) ----------------
__device__ float4 g_p4_0[N0];
__device__ float4 g_p4_1[N1];
__device__ float4 g_p4_2[N2];
__device__ float4 g_p4_3[N3];
__device__ int    g_sel0[N1];
__device__ int    g_sel1[N2];
__device__ int    g_sel2[N3];
__device__ int    g_sori[N0];
__device__ float4 g_h0[N0 * 4];
__device__ float4 g_x1[N1 * 4];
__device__ float4 g_x2[N2 * 4];
__device__ float4 g_x3[N3 * 4];
__device__ float4 g_f2[N2 * 4];
__device__ float4 g_f1[N1 * 4];
__device__ float4 g_f0[N0 * 4];

// ---------------- packed f32x2 helpers ----------------
__device__ __forceinline__ unsigned long long pk2(float lo, float hi) {
    unsigned long long r;
    asm("mov.b64 %0, {%1, %2};" : "=l"(r) : "f"(lo), "f"(hi));
    return r;
}
__device__ __forceinline__ void unpk2(unsigned long long v, float& lo, float& hi) {
    asm("mov.b64 {%0, %1}, %2;" : "=f"(lo), "=f"(hi) : "l"(v));
}
__device__ __forceinline__ unsigned long long add2(unsigned long long a, unsigned long long b) {
    unsigned long long r;
    asm("add.rn.f32x2 %0, %1, %2;" : "=l"(r) : "l"(a), "l"(b));
    return r;
}
__device__ __forceinline__ unsigned long long mul2(unsigned long long a, unsigned long long b) {
    unsigned long long r;
    asm("mul.rn.f32x2 %0, %1, %2;" : "=l"(r) : "l"(a), "l"(b));
    return r;
}

// ---------------- prep ----------------
__global__ void prep_kernel(const float* __restrict__ pos) {
    int i = blockIdx.x * blockDim.x + threadIdx.x;
    if (i >= N0) return;
    float x = pos[3 * i], y = pos[3 * i + 1], z = pos[3 * i + 2];
    float nb = __fadd_rn(__fadd_rn(__fmul_rn(x, x), __fmul_rn(y, y)), __fmul_rn(z, z));
    g_p4_0[i] = make_float4(x, y, z, nb);
}

__global__ void warm_kernel() {}

__device__ __forceinline__ void load16(const float4* __restrict__ row, float* v) {
    float4 a = row[0], b = row[1], c = row[2], d = row[3];
    v[0] = a.x; v[1] = a.y; v[2] = a.z; v[3] = a.w;
    v[4] = b.x; v[5] = b.y; v[6] = b.z; v[7] = b.w;
    v[8] = c.x; v[9] = c.y; v[10] = c.z; v[11] = c.w;
    v[12] = d.x; v[13] = d.y; v[14] = d.z; v[15] = d.w;
}

__device__ __forceinline__ void store16(float4* __restrict__ row, const float* v) {
    row[0] = make_float4(v[0], v[1], v[2], v[3]);
    row[1] = make_float4(v[4], v[5], v[6], v[7]);
    row[2] = make_float4(v[8], v[9], v[10], v[11]);
    row[3] = make_float4(v[12], v[13], v[14], v[15]);
}

// ---------------- lin_in body (1024-thread blocks) ----------------
__device__ void lin_in_body(const float* __restrict__ x,
                            const float* __restrict__ W0, const float* __restrict__ b0,
                            const float* __restrict__ W1, const float* __restrict__ b1,
                            int g) {
    __shared__ float sW0[256], sW1[256], sb0[16], sb1[16];
    int t = threadIdx.x;
    if (t < 256) { sW0[t] = W0[t]; sW1[t] = W1[t]; }
    if (t < 16) { sb0[t] = b0[t]; sb1[t] = b1[t]; }
    __syncthreads();
    if (g >= N0) return;
    float in[16], hid[16], out[16];
    load16((const float4*)(x + g * 16), in);
#pragma unroll
    for (int o = 0; o < 16; o++) hid[o] = sb0[o];
#pragma unroll
    for (int i = 0; i < 16; i++) {
        float v = in[i];
#pragma unroll
        for (int o = 0; o < 16; o++) hid[o] = fmaf(v, sW0[i * 16 + o], hid[o]);
    }
#pragma unroll
    for (int o = 0; o < 16; o++) hid[o] = fmaxf(hid[o], 0.0f);
#pragma unroll
    for (int o = 0; o < 16; o++) out[o] = sb1[o];
#pragma unroll
    for (int i = 0; i < 16; i++) {
        float v = hid[i];
#pragma unroll
        for (int o = 0; o < 16; o++) out[o] = fmaf(v, sW1[i * 16 + o], out[o]);
    }
#pragma unroll
    for (int o = 0; o < 16; o++) out[o] = fmaxf(out[o], 0.0f);
    store16(&g_h0[g * 4], out);
}

// ---------------- FPS helpers ----------------
template <int GB>
__device__ __forceinline__ int mcell(float x, float y, float z) {
    const float inv = (float)(1 << GB) * (1.0f / 32.0f);
    int cx = min((1 << GB) - 1, max(0, (int)(x * inv)));
    int cy = min((1 << GB) - 1, max(0, (int)(y * inv)));
    int cz = min((1 << GB) - 1, max(0, (int)(z * inv)));
    int m = 0;
#pragma unroll
    for (int b = 0; b < GB; b++)
        m |= (((cx >> b) & 1) << (3 * b)) | (((cy >> b) & 1) << (3 * b + 1)) |
             (((cz >> b) & 1) << (3 * b + 2));
    return m;
}

template <int LOGP>
__device__ __forceinline__ int pair_fidx(int tt, int kk) {
    return (kk >> 1) * (2 * FPS_T) + 2 * tt + (kk & 1);
}

// ---------------- FPS body: EXACT copy of the R10 (8570.6us) kernel ----------------
template <int NPTS, int M, int PTS, int GB>
__device__ void fps_body(const float4* __restrict__ p4, int* __restrict__ sel,
                         int* __restrict__ sori, float* sm) {
    constexpr int NCELL = 1 << (3 * GB);
    constexpr int LOGP = (PTS == 16) ? 4 : (PTS == 8) ? 3 : 2;
    __shared__ int s_hist[4096];
    __shared__ unsigned s_val[32];
    __shared__ int s_si[32];
    __shared__ float4 s_ctrv;
    __shared__ int s_misc[40];

    float* px = sm;
    float* py = sm + NPTS;
    float* pz = sm + 2 * NPTS;

    const int t = threadIdx.x;
    const int lane = t & 31;
    const int wid = t >> 5;

    // ---- phase 1: histogram ----
    for (int i = t; i < NCELL; i += FPS_T) s_hist[i] = 0;
    __syncthreads();
    for (int i = t; i < NPTS; i += FPS_T) {
        float4 p = p4[i];
        atomicAdd(&s_hist[mcell<GB>(p.x, p.y, p.z)], 1);
    }
    __syncthreads();

    // ---- phase 2: exclusive block scan ----
    {
        constexpr int PER = (NCELL + FPS_T - 1) / FPS_T;
        int base = t * PER;
        int vals[PER];
        int run = 0;
#pragma unroll
        for (int q = 0; q < PER; q++) {
            int v = (base + q < NCELL) ? s_hist[base + q] : 0;
            vals[q] = v;
            run += v;
        }
        int inc = run;
#pragma unroll
        for (int off = 1; off < 32; off <<= 1) {
            int nb = __shfl_up_sync(0xffffffffu, inc, off);
            if (lane >= off) inc += nb;
        }
        if (lane == 31) s_misc[8 + wid] = inc;
        __syncthreads();
        if (t < 32) {
            int w = s_misc[8 + t];
            int winc = w;
#pragma unroll
            for (int off = 1; off < 32; off <<= 1) {
                int nb = __shfl_up_sync(0xffffffffu, winc, off);
                if (t >= off) winc += nb;
            }
            s_misc[8 + t] = winc - w;
        }
        __syncthreads();
        int off0 = s_misc[8 + wid] + (inc - run);
#pragma unroll
        for (int q = 0; q < PER; q++) {
            if (base + q < NCELL) s_hist[base + q] = off0;
            off0 += vals[q];
        }
    }
    __syncthreads();

    // ---- phase 3: scatter into pair-interleaved smem layout ----
    for (int i = t; i < NPTS; i += FPS_T) {
        float4 p = p4[i];
        int d = atomicAdd(&s_hist[mcell<GB>(p.x, p.y, p.z)], 1);
        int tt = d >> LOGP;
        int kk = d & (PTS - 1);
        int fidx = pair_fidx<LOGP>(tt, kk);
        px[fidx] = p.x; py[fidx] = p.y; pz[fidx] = p.z;
        sori[d] = i;
        if (i == 0) s_misc[0] = d;
    }
    __syncthreads();

    // ---- phase 4: per-thread mind init + WARP-level AABB ----
    float mind[PTS];
    float lox = CUDART_INF_F, loy = CUDART_INF_F, loz = CUDART_INF_F;
    float hix = -CUDART_INF_F, hiy = -CUDART_INF_F, hiz = -CUDART_INF_F;
#pragma unroll
    for (int k = 0; k < PTS; k++) {
        int fidx = pair_fidx<LOGP>(t, k);
        float X = px[fidx], Y = py[fidx], Z = pz[fidx];
        lox = fminf(lox, X); hix = fmaxf(hix, X);
        loy = fminf(loy, Y); hiy = fmaxf(hiy, Y);
        loz = fminf(loz, Z); hiz = fmaxf(hiz, Z);
        mind[k] = CUDART_INF_F;
    }
#pragma unroll
    for (int off = 16; off; off >>= 1) {
        lox = fminf(lox, __shfl_xor_sync(0xffffffffu, lox, off));
        hix = fmaxf(hix, __shfl_xor_sync(0xffffffffu, hix, off));
        loy = fminf(loy, __shfl_xor_sync(0xffffffffu, loy, off));
        hiy = fmaxf(hiy, __shfl_xor_sync(0xffffffffu, hiy, off));
        loz = fminf(loz, __shfl_xor_sync(0xffffffffu, loz, off));
        hiz = fmaxf(hiz, __shfl_xor_sync(0xffffffffu, hiz, off));
    }

    float wbest = CUDART_INF_F;
    if (lane == 0) { s_val[wid] = __float_as_uint(CUDART_INF_F); s_si[wid] = wid * 32 * PTS; }

    // prologue: publish the first center (original point 0)
    if (wid == 0) {
        int j0 = s_misc[0];
        int fidx = pair_fidx<LOGP>(j0 >> LOGP, j0 & (PTS - 1));
        if (lane < 3) {
            float cv = (lane == 0) ? px[fidx] : (lane == 1) ? py[fidx] : pz[fidx];
            ((float*)&s_ctrv)[lane] = cv;
        }
        if (lane == 0) sel[0] = j0;
    }
    __syncthreads();

    // ---- phase 5: the FPS scan ----
    for (int step = 1; step < M; ++step) {
        float4 c = s_ctrv;

        float ax = fmaxf(fmaxf(lox - c.x, c.x - hix), 0.0f);
        float ay = fmaxf(fmaxf(loy - c.y, c.y - hiy), 0.0f);
        float az = fmaxf(fmaxf(loz - c.z, c.z - hiz), 0.0f);
        float lb = fmaf(ax, ax, fmaf(ay, ay, az * az)) * 0.9999f;

        if (lb < wbest) {
            unsigned long long ncx2 = pk2(-c.x, -c.x);
            unsigned long long ncy2 = pk2(-c.y, -c.y);
            unsigned long long ncz2 = pk2(-c.z, -c.z);
            float bv = -CUDART_INF_F;
#pragma unroll
            for (int k2 = 0; k2 < PTS / 2; k2++) {
                int base = k2 * (2 * FPS_T) + 2 * t;
                unsigned long long X = *(const unsigned long long*)(px + base);
                unsigned long long Y = *(const unsigned long long*)(py + base);
                unsigned long long Z = *(const unsigned long long*)(pz + base);
                unsigned long long dX = add2(X, ncx2);
                unsigned long long dY = add2(Y, ncy2);
                unsigned long long dZ = add2(Z, ncz2);
                unsigned long long s2 = add2(add2(mul2(dX, dX), mul2(dY, dY)), mul2(dZ, dZ));
                float d2a, d2b;
                unpk2(s2, d2a, d2b);
                float mna = fminf(mind[2 * k2], d2a);
                mind[2 * k2] = mna;
                float mnb = fminf(mind[2 * k2 + 1], d2b);
                mind[2 * k2 + 1] = mnb;
                bv = fmaxf(bv, fmaxf(mna, mnb));
            }
            unsigned msk = 0u;
#pragma unroll
            for (int k = 0; k < PTS; k++)
                if (mind[k] == bv) msk |= (1u << k);
            int csi = t * PTS + (__ffs(msk) - 1);

            unsigned mybits = __float_as_uint(bv);
            unsigned wmax = __reduce_max_sync(0xffffffffu, mybits);
            unsigned who = __ballot_sync(0xffffffffu, mybits == wmax);
            int src = __ffs(who) - 1;
            int wsi = __shfl_sync(0xffffffffu, csi, src);
            wbest = __uint_as_float(wmax);
            if (lane == 0) { s_val[wid] = wmax; s_si[wid] = wsi; }
        }
        __syncthreads();   // bar1

        if (wid == 0) {
            unsigned v = s_val[lane];
            unsigned bmax = __reduce_max_sync(0xffffffffu, v);
            unsigned wwin = __ballot_sync(0xffffffffu, v == bmax);
            int widwin = __ffs(wwin) - 1;
            int si = s_si[widwin];
            int fidx = pair_fidx<LOGP>(si >> LOGP, si & (PTS - 1));
            if (lane < 3) {
                float cv = (lane == 0) ? px[fidx] : (lane == 1) ? py[fidx] : pz[fidx];
                ((float*)&s_ctrv)[lane] = cv;
            }
            if (lane == 0) sel[step] = si;
        }
        __syncthreads();   // bar2
    }

    // ---- phase 6: remap ----
    for (int i = t; i < M; i += FPS_T) {
        int si_ = sel[i];
        sel[i] = sori[si_];
    }
}

// ---------------- SA body (1024-thread blocks, 32 targets/block) ----------------
template <int NSRC>
__device__ void sa_body(const float4* __restrict__ p4s, const float4* __restrict__ p4t,
                        const float4* __restrict__ hs, float4* __restrict__ xt,
                        const float* __restrict__ W0, const float* __restrict__ b0,
                        const float* __restrict__ W1, const float* __restrict__ b1,
                        int ntgt, int tgt_base) {
    __shared__ float sW0[19 * 19], sW1[19 * 16], sb0[19], sb1[16];
    int t = threadIdx.x;
    if (t < 361) sW0[t] = W0[t];
    else if (t < 665) sW1[t - 361] = W1[t - 361];
    else if (t < 684) sb0[t - 665] = b0[t - 665];
    else if (t < 700) sb1[t - 684] = b1[t - 684];
    __syncthreads();

    int lane = t & 31;
    int warp = tgt_base + (t >> 5);
    if (warp >= ntgt) return;

    float4 pt = p4t[warp];
    float na = pt.w;
    float myd = 0.0f;
    int myj = 0;
    int cnt = 0;

    for (int base = 0; base < NSRC; base += 32) {
        int j = base + lane;
        float4 ps = p4s[j];
        float dot = fmaf(pt.x, ps.x, fmaf(pt.y, ps.y, pt.z * ps.z));
        float d2 = fmaxf((na + ps.w) - 2.0f * dot, 0.0f);
        bool hit = d2 <= R2C;
        unsigned mm = __ballot_sync(0xffffffffu, hit);
        while (mm) {
            int b = __ffs(mm) - 1;
            mm &= mm - 1;
            float nd = __shfl_sync(0xffffffffu, d2, b);
            int nj = base + b;
            if (cnt < 32) {
                if (lane == cnt) { myd = nd; myj = nj; }
                cnt++;
            } else {
                float mv = (lane < cnt) ? myd : -CUDART_INF_F;
                int ml = lane;
#pragma unroll
                for (int off = 16; off; off >>= 1) {
                    float ov = __shfl_xor_sync(0xffffffffu, mv, off);
                    int ol = __shfl_xor_sync(0xffffffffu, ml, off);
                    if (ov > mv) { mv = ov; ml = ol; }
                }
                if (nd < mv && lane == ml) { myd = nd; myj = nj; }
            }
        }
    }

    bool valid = lane < cnt;
    int jj = valid ? myj : 0;
    float in[19];
    load16(&hs[jj * 4], in);
    float4 sp = p4s[jj];
    in[16] = sp.x - pt.x;
    in[17] = sp.y - pt.y;
    in[18] = sp.z - pt.z;

    float hid[19];
#pragma unroll
    for (int o = 0; o < 19; o++) hid[o] = sb0[o];
#pragma unroll
    for (int i = 0; i < 19; i++) {
        float v = in[i];
#pragma unroll
        for (int o = 0; o < 19; o++) hid[o] = fmaf(v, sW0[i * 19 + o], hid[o]);
    }
#pragma unroll
    for (int o = 0; o < 19; o++) hid[o] = fmaxf(hid[o], 0.0f);

    float out[16];
#pragma unroll
    for (int o = 0; o < 16; o++) out[o] = sb1[o];
#pragma unroll
    for (int i = 0; i < 19; i++) {
        float v = hid[i];
#pragma unroll
        for (int o = 0; o < 16; o++) out[o] = fmaf(v, sW1[i * 16 + o], out[o]);
    }
    float res[16];
#pragma unroll
    for (int c = 0; c < 16; c++) {
        float r = valid ? fmaxf(out[c], 0.0f) : -CUDART_INF_F;
#pragma unroll
        for (int off = 16; off; off >>= 1) r = fmaxf(r, __shfl_xor_sync(0xffffffffu, r, off));
        res[c] = r;
    }
    if (lane == 0) store16(&xt[warp * 4], res);
}

// ---------------- fused kernels ----------------
__global__ __launch_bounds__(FPS_T, 1)
void fused_fps0_linin(const float4* __restrict__ p4, int* __restrict__ sel,
                      int* __restrict__ sori, const float* __restrict__ x,
                      const float* __restrict__ liW0, const float* __restrict__ lib0,
                      const float* __restrict__ liW1, const float* __restrict__ lib1) {
    extern __shared__ float sm[];
    if (blockIdx.x == 0) {
        fps_body<N0, N1, 16, 4>(p4, sel, sori, sm);
    } else {
        lin_in_body(x, liW0, lib0, liW1, lib1, (blockIdx.x - 1) * FPS_T + threadIdx.x);
    }
}

template <int NPTS, int M, int PTS, int GB, int NSRC>
__global__ __launch_bounds__(FPS_T, 1)
void fused_fps_sa(const float4* __restrict__ p4f, int* __restrict__ sel,
                  int* __restrict__ sori,
                  const float4* __restrict__ p4s, const float4* __restrict__ p4t,
                  const float4* __restrict__ hs, float4* __restrict__ xt,
                  const float* __restrict__ W0, const float* __restrict__ b0,
                  const float* __restrict__ W1, const float* __restrict__ b1, int ntgt) {
    extern __shared__ float sm[];
    if (blockIdx.x == 0) {
        fps_body<NPTS, M, PTS, GB>(p4f, sel, sori, sm);
    } else {
        sa_body<NSRC>(p4s, p4t, hs, xt, W0, b0, W1, b1, ntgt, (blockIdx.x - 1) * 32);
    }
}

template <int NSRC>
__global__ __launch_bounds__(FPS_T, 1)
void sa_only_kernel(const float4* __restrict__ p4s, const float4* __restrict__ p4t,
                    const float4* __restrict__ hs, float4* __restrict__ xt,
                    const float* __restrict__ W0, const float* __restrict__ b0,
                    const float* __restrict__ W1, const float* __restrict__ b1, int ntgt) {
    sa_body<NSRC>(p4s, p4t, hs, xt, W0, b0, W1, b1, ntgt, blockIdx.x * 32);
}

// ---------------- gather ----------------
__global__ void gather_kernel(const float4* __restrict__ src, const int* __restrict__ sel,
                              float4* __restrict__ dst, int m) {
    int i = blockIdx.x * blockDim.x + threadIdx.x;
    if (i < m) dst[i] = src[sel[i]];
}

// ---------------- FP: kNN(3) interpolate + MLP(32->32->16) ----------------
template <int NC>
__global__ void fp_kernel(const float4* __restrict__ p4f, const float4* __restrict__ p4c,
                          const float4* __restrict__ xc, const float4* __restrict__ xs,
                          float4* __restrict__ xf,
                          const float* __restrict__ W0, const float* __restrict__ b0,
                          const float* __restrict__ W1, const float* __restrict__ b1,
                          int nf) {
    __shared__ float sW0[32 * 32], sW1[32 * 16], sb0[32], sb1[16];
    int t = threadIdx.x;
    for (int i = t; i < 1024; i += blockDim.x) sW0[i] = W0[i];
    for (int i = t; i < 512; i += blockDim.x) sW1[i] = W1[i];
    if (t < 32) sb0[t] = b0[t];
    if (t < 16) sb1[t] = b1[t];
    __syncthreads();

    int g = blockIdx.x * blockDim.x + t;
    if (g >= nf) return;
    float4 f = p4f[g];
    float na = f.w;
    float d0 = CUDART_INF_F, d1 = CUDART_INF_F, d2 = CUDART_INF_F;
    int i0 = 0, i1 = 0, i2 = 0;
    for (int j = 0; j < NC; j++) {
        float4 c = p4c[j];
        float dot = fmaf(f.x, c.x, fmaf(f.y, c.y, f.z * c.z));
        float dd = fmaxf((na + c.w) - 2.0f * dot, 0.0f);
        if (dd < d0) {
            d2 = d1; i2 = i1; d1 = d0; i1 = i0; d0 = dd; i0 = j;
        } else if (dd < d1) {
            d2 = d1; i2 = i1; d1 = dd; i1 = j;
        } else if (dd < d2) {
            d2 = dd; i2 = j;
        }
    }
    float w0 = 1.0f / fmaxf(d0, 1e-16f);
    float w1 = 1.0f / fmaxf(d1, 1e-16f);
    float w2 = 1.0f / fmaxf(d2, 1e-16f);
    float ws = w0 + w1 + w2;
    w0 /= ws; w1 /= ws; w2 /= ws;

    float a0[16], a1[16], a2[16], in[32];
    load16(&xc[i0 * 4], a0);
    load16(&xc[i1 * 4], a1);
    load16(&xc[i2 * 4], a2);
#pragma unroll
    for (int c = 0; c < 16; c++) in[c] = (a0[c] * w0 + a1[c] * w1) + a2[c] * w2;
    load16(&xs[g * 4], in + 16);

    float hid[32];
#pragma unroll
    for (int o = 0; o < 32; o++) hid[o] = sb0[o];
#pragma unroll
    for (int i = 0; i < 32; i++) {
        float v = in[i];
#pragma unroll
        for (int o = 0; o < 32; o++) hid[o] = fmaf(v, sW0[i * 32 + o], hid[o]);
    }
#pragma unroll
    for (int o = 0; o < 32; o++) hid[o] = fmaxf(hid[o], 0.0f);
    float out[16];
#pragma unroll
    for (int o = 0; o < 16; o++) out[o] = sb1[o];
#pragma unroll
    for (int i = 0; i < 32; i++) {
        float v = hid[i];
#pragma unroll
        for (int o = 0; o < 16; o++) out[o] = fmaf(v, sW1[i * 16 + o], out[o]);
    }
#pragma unroll
    for (int o = 0; o < 16; o++) out[o] = fmaxf(out[o], 0.0f);
    store16(&xf[g * 4], out);
}

// ---------------- lin_out ----------------
__global__ void lin_out_kernel(const float* __restrict__ W0, const float* __restrict__ b0,
                               const float* __restrict__ W1, const float* __restrict__ b1,
                               float* __restrict__ out) {
    __shared__ float sW0[256], sW1[32], sb0[16], sb1[2];
    int t = threadIdx.x;
    for (int i = t; i < 256; i += blockDim.x) sW0[i] = W0[i];
    if (t < 32) sW1[t] = W1[t];
    if (t < 16) sb0[t] = b0[t];
    if (t < 2) sb1[t] = b1[t];
    __syncthreads();
    int g = blockIdx.x * blockDim.x + t;
    if (g >= N0) return;
    float in[16], hid[16];
    load16(&g_f0[g * 4], in);
#pragma unroll
    for (int o = 0; o < 16; o++) hid[o] = sb0[o];
#pragma unroll
    for (int i = 0; i < 16; i++) {
        float v = in[i];
#pragma unroll
        for (int o = 0; o < 16; o++) hid[o] = fmaf(v, sW0[i * 16 + o], hid[o]);
    }
    float o0 = sb1[0], o1 = sb1[1];
#pragma unroll
    for (int i = 0; i < 16; i++) {
        float v = fmaxf(hid[i], 0.0f);
        o0 = fmaf(v, sW1[i * 2 + 0], o0);
        o1 = fmaf(v, sW1[i * 2 + 1], o1);
    }
    out[g * 2 + 0] = o0;
    out[g * 2 + 1] = o1;
}

// ---------------- host launcher ----------------
extern "C" void kernel_launch(void* const* d_in, const int* in_sizes, int n_in,
                              void* d_out, int out_size) {
    const float* x = (const float*)d_in[0];
    const float* pos = (const float*)d_in[1];
    const float* liW0 = (const float*)d_in[3];
    const float* lib0 = (const float*)d_in[4];
    const float* liW1 = (const float*)d_in[5];
    const float* lib1 = (const float*)d_in[6];
    const float* saW0 = (const float*)d_in[7];
    const float* sab0 = (const float*)d_in[8];
    const float* saW1 = (const float*)d_in[9];
    const float* sab1 = (const float*)d_in[10];
    const float* fpW0 = (const float*)d_in[11];
    const float* fpb0 = (const float*)d_in[12];
    const float* fpW1 = (const float*)d_in[13];
    const float* fpb1 = (const float*)d_in[14];
    const float* loW0 = (const float*)d_in[15];
    const float* lob0 = (const float*)d_in[16];
    const float* loW1 = (const float*)d_in[17];
    const float* lob1 = (const float*)d_in[18];
    float* out = (float*)d_out;

    void *p40, *p41, *p42, *p43, *s0, *s1, *s2, *sori, *h0, *x1, *x2, *x3, *f2, *f1, *f0;
    cudaGetSymbolAddress(&p40, g_p4_0);
    cudaGetSymbolAddress(&p41, g_p4_1);
    cudaGetSymbolAddress(&p42, g_p4_2);
    cudaGetSymbolAddress(&p43, g_p4_3);
    cudaGetSymbolAddress(&s0, g_sel0);
    cudaGetSymbolAddress(&s1, g_sel1);
    cudaGetSymbolAddress(&s2, g_sel2);
    cudaGetSymbolAddress(&sori, g_sori);
    cudaGetSymbolAddress(&h0, g_h0);
    cudaGetSymbolAddress(&x1, g_x1);
    cudaGetSymbolAddress(&x2, g_x2);
    cudaGetSymbolAddress(&x3, g_x3);
    cudaGetSymbolAddress(&f2, g_f2);
    cudaGetSymbolAddress(&f1, g_f1);
    cudaGetSymbolAddress(&f0, g_f0);

    size_t sm0 = (size_t)N0 * 12;
    size_t sm1 = (size_t)N1 * 12;
    size_t sm2 = (size_t)N2 * 12;
    cudaFuncSetAttribute((const void*)fused_fps0_linin,
                         cudaFuncAttributeMaxDynamicSharedMemorySize, (int)sm0);
    cudaFuncSetAttribute((const void*)fused_fps_sa<N1, N2, 8, 3, N0>,
                         cudaFuncAttributeMaxDynamicSharedMemorySize, (int)sm1);
    cudaFuncSetAttribute((const void*)fused_fps_sa<N2, N3, 4, 3, N1>,
                         cudaFuncAttributeMaxDynamicSharedMemorySize, (int)sm2);

    prep_kernel<<<(N0 + 255) / 256, 256>>>(pos);
    warm_kernel<<<1, 32>>>();

    // fps0 (block 0) runs concurrently with lin_in (blocks 1..16)
    fused_fps0_linin<<<1 + N0 / FPS_T, FPS_T, sm0>>>(
        (const float4*)p40, (int*)s0, (int*)sori, x, liW0, lib0, liW1, lib1);
    gather_kernel<<<N1 / 256, 256>>>((const float4*)p40, (const int*)s0, (float4*)p41, N1);

    // fps1 (block 0) runs concurrently with sa_conv level-0 (blocks 1..256)
    fused_fps_sa<N1, N2, 8, 3, N0><<<1 + N1 / 32, FPS_T, sm1>>>(
        (const float4*)p41, (int*)s1, (int*)sori,
        (const float4*)p40, (const float4*)p41, (const float4*)h0, (float4*)x1,
        saW0, sab0, saW1, sab1, N1);
    gather_kernel<<<N2 / 256, 256>>>((const float4*)p41, (const int*)s1, (float4*)p42, N2);

    // fps2 (block 0) runs concurrently with sa_conv level-1 (blocks 1..128)
    fused_fps_sa<N2, N3, 4, 3, N1><<<1 + N2 / 32, FPS_T, sm2>>>(
        (const float4*)p42, (int*)s2, (int*)sori,
        (const float4*)p41, (const float4*)p42, (const float4*)x1, (float4*)x2,
        saW0 + 361, sab0 + 19, saW1 + 304, sab1 + 16, N2);
    gather_kernel<<<N3 / 256, 256>>>((const float4*)p42, (const int*)s2, (float4*)p43, N3);

    // sa_conv level-2 (after fps2)
    sa_only_kernel<N2><<<N3 / 32, FPS_T>>>(
        (const float4*)p42, (const float4*)p43, (const float4*)x2, (float4*)x3,
        saW0 + 722, sab0 + 38, saW1 + 608, sab1 + 32, N3);

    // FP path (coarse -> fine)
    fp_kernel<N3><<<N2 / 128, 128>>>((const float4*)p42, (const float4*)p43,
                                     (const float4*)x3, (const float4*)x2, (float4*)f2,
                                     fpW0 + 2 * 1024, fpb0 + 2 * 32, fpW1 + 2 * 512, fpb1 + 2 * 16,
                                     N2);
    fp_kernel<N2><<<N1 / 128, 128>>>((const float4*)p41, (const float4*)p42,
                                     (const float4*)f2, (const float4*)x1, (float4*)f1,
                                     fpW0 + 1024, fpb0 + 32, fpW1 + 512, fpb1 + 16, N1);
    fp_kernel<N1><<<N0 / 128, 128>>>((const float4*)p40, (const float4*)p41,
                                     (const float4*)f1, (const float4*)h0, (float4*)f0,
                                     fpW0, fpb0, fpW1, fpb1, N0);

    lin_out_kernel<<<N0 / 256, 256>>>(loW0, lob0, loW1, lob1, out);
}